// round 5
// baseline (speedup 1.0000x reference)
#include <cuda_runtime.h>
#include <cuda_bf16.h>
#include <math.h>
#include <stdint.h>

// ---------------- problem constants ----------------
#define D_      768
#define B_      32
#define N_      1024
#define I_      64
#define S_      4
#define RPB     (I_ * S_)        // 256 rows per batch item
#define R_      (B_ * RPB)       // 8192 total slot rows
#define D2_     (2 * D_)         // 1536

typedef __nv_bfloat16 bf;

// ---------------- scratch (device globals; no allocs allowed) ----------------
__device__ __align__(16) bf g_tokh[(size_t)B_ * N_ * D_];
__device__ __align__(16) bf g_tokl[(size_t)B_ * N_ * D_];
__device__ __align__(16) bf g_kh[(size_t)B_ * N_ * D_];
__device__ __align__(16) bf g_kl[(size_t)B_ * N_ * D_];
__device__ __align__(16) bf g_vTh[(size_t)B_ * D_ * N_];
__device__ __align__(16) bf g_vTl[(size_t)B_ * D_ * N_];
__device__ __align__(16) bf g_Wkh[D_ * D_], g_Wkl[D_ * D_];
__device__ __align__(16) bf g_Wvh[D_ * D_], g_Wvl[D_ * D_];
__device__ __align__(16) bf g_Wqsh[D_ * D_], g_Wqsl[D_ * D_];
__device__ __align__(16) bf g_Wqih[D_ * D_], g_Wqil[D_ * D_];
__device__ __align__(16) bf g_W1h[D2_ * D_], g_W1l[D2_ * D_];
__device__ __align__(16) bf g_W2h[D_ * D2_], g_W2l[D_ * D2_];
__device__ __align__(16) bf g_iqh[I_ * D_], g_iql[I_ * D_];
__device__ __align__(16) bf g_sh[(size_t)R_ * D_], g_sl[(size_t)R_ * D_];
__device__ __align__(16) bf g_qsh[(size_t)R_ * D_], g_qsl[(size_t)R_ * D_];
__device__ __align__(16) bf g_ah[(size_t)R_ * N_], g_al[(size_t)R_ * N_];
__device__ __align__(16) bf g_hlnh[(size_t)R_ * D_], g_hlnl[(size_t)R_ * D_];
__device__ __align__(16) bf g_hmh[(size_t)R_ * D2_], g_hml[(size_t)R_ * D2_];
__device__ __align__(16) float g_qint[I_ * D_];
__device__ __align__(16) float g_slots[(size_t)R_ * D_];
__device__ __align__(16) float g_logits[(size_t)R_ * N_];
__device__ __align__(16) float g_upd[(size_t)R_ * D_];

// ---------------- helpers ----------------
__device__ __forceinline__ uint32_t smem_u32(const void* p) {
    uint32_t a;
    asm("{ .reg .u64 t; cvta.to.shared.u64 t, %1; cvt.u32.u64 %0, t; }" : "=r"(a) : "l"(p));
    return a;
}

__device__ __forceinline__ void mma16816(float* c, const uint32_t* a, const uint32_t* b) {
    asm volatile(
        "mma.sync.aligned.m16n8k16.row.col.f32.bf16.bf16.f32 "
        "{%0,%1,%2,%3}, {%4,%5,%6,%7}, {%8,%9}, {%0,%1,%2,%3};"
        : "+f"(c[0]), "+f"(c[1]), "+f"(c[2]), "+f"(c[3])
        : "r"(a[0]), "r"(a[1]), "r"(a[2]), "r"(a[3]), "r"(b[0]), "r"(b[1]));
}

// ---------------- mma.sync bf16x3 GEMM v2 ----------------
// C[M,N] = op(A[M,K] x B[N,K]^T); A/B pre-split bf16 hi/lo planes (K-contiguous).
// Block tile 256x128 (8 warps x 64x64), BK=32, cp.async double-buffered smem.
// 3 passes AhBh + AhBl + AlBh into fp32 accum (err ~1e-5).
// MODE: 0 plain | 1 +bias[c] | 2 +bias[c]+qint[intent(r)][c] | 3 *alpha
//       4 gelu(x+bias[c]) | 5 +bias[c]+extra[r*N+c] | 6 +bias[r]
#define BM2   256
#define BN2   128
#define BK2   32
#define RSTR  40                     // padded row stride in elems (80B, conflict-free)
#define A_PLANE_B  (BM2 * RSTR * 2)  // 20480 B
#define B_PLANE_B  (BN2 * RSTR * 2)  // 10240 B
#define STG_BYTES  (2 * A_PLANE_B + 2 * B_PLANE_B)  // 61440
#define GM_SMEM    (2 * STG_BYTES)                  // 122880

template<int MODE, bool OUTF, bool OUTH>
__global__ __launch_bounds__(256, 1)
void gemm2(const bf* __restrict__ Ah, const bf* __restrict__ Al,
           const bf* __restrict__ Bh, const bf* __restrict__ Bl,
           float* __restrict__ Cf, bf* __restrict__ Ch, bf* __restrict__ Cl,
           int M, int N, int K, long sA, long sB, long sC,
           const float* __restrict__ bias, const float* __restrict__ extra, float alpha)
{
    extern __shared__ __align__(16) char smem[];
    const uint32_t sbase = smem_u32(smem);

    const int tid  = threadIdx.x;
    const int warp = tid >> 5;
    const int lane = tid & 31;
    const int gr   = lane >> 2;   // 0..7
    const int qp   = lane & 3;    // 0..3
    const int wm   = warp >> 1;   // 0..3 -> m offset wm*64
    const int wn   = warp & 1;    // 0..1 -> n offset wn*64

    const long z = blockIdx.z;
    Ah += z * sA; Al += z * sA;
    Bh += z * sB; Bl += z * sB;

    const int row0 = blockIdx.y * BM2;
    const int col0 = blockIdx.x * BN2;
    const int T = K / BK2;

    // ---- stage loader: 12 cp.async x 16B per thread ----
    auto load_stage = [&](int stg, int k0) {
        const uint32_t s0 = sbase + stg * STG_BYTES;
        #pragma unroll
        for (int i = 0; i < 12; i++) {
            int c = tid + i * 256;               // 0..3071
            if (c < 2048) {                      // A planes: hi then lo
                int plane = c >> 10;
                int rc = c & 1023;
                int r  = rc >> 2;
                int ch = rc & 3;
                uint32_t dst = s0 + plane * A_PLANE_B + r * 80 + ch * 16;
                const bf* Ap = plane ? Al : Ah;
                int grow = row0 + r;
                int ok = grow < M;
                const char* src = (const char*)(Ap + (long)(ok ? grow : row0) * K + k0) + ch * 16;
                int sz = ok ? 16 : 0;
                asm volatile("cp.async.cg.shared.global [%0], [%1], 16, %2;"
                             :: "r"(dst), "l"(src), "r"(sz));
            } else {                             // B planes
                int c2 = c - 2048;
                int plane = c2 >> 9;
                int rc = c2 & 511;
                int r  = rc >> 2;
                int ch = rc & 3;
                uint32_t dst = s0 + 2 * A_PLANE_B + plane * B_PLANE_B + r * 80 + ch * 16;
                const bf* Bp = plane ? Bl : Bh;
                const char* src = (const char*)(Bp + (long)(col0 + r) * K + k0) + ch * 16;
                asm volatile("cp.async.cg.shared.global [%0], [%1], 16;"
                             :: "r"(dst), "l"(src));
            }
        }
        asm volatile("cp.async.commit_group;" ::: "memory");
    };

    float acc[4][8][4];
    #pragma unroll
    for (int i = 0; i < 4; i++)
        #pragma unroll
        for (int j = 0; j < 8; j++)
            #pragma unroll
            for (int q = 0; q < 4; q++) acc[i][j][q] = 0.0f;

    load_stage(0, 0);
    load_stage(1, BK2);

    for (int t = 0; t < T; t++) {
        if (t < T - 1) asm volatile("cp.async.wait_group 1;" ::: "memory");
        else           asm volatile("cp.async.wait_group 0;" ::: "memory");
        __syncthreads();

        const bf* sAh = (const bf*)(smem + (t & 1) * STG_BYTES);
        const bf* sAl = (const bf*)(smem + (t & 1) * STG_BYTES + A_PLANE_B);
        const bf* sBh = (const bf*)(smem + (t & 1) * STG_BYTES + 2 * A_PLANE_B);
        const bf* sBl = (const bf*)(smem + (t & 1) * STG_BYTES + 2 * A_PLANE_B + B_PLANE_B);

        #pragma unroll
        for (int ks = 0; ks < 2; ks++) {
            const int c0 = ks * 16 + 2 * qp;
            const int c2 = c0 + 8;

            // B fragments for all 8 jn columns (hi + lo)
            uint32_t Bhf[8][2], Blf[8][2];
            #pragma unroll
            for (int jn = 0; jn < 8; jn++) {
                int rb = wn * 64 + jn * 8 + gr;
                Bhf[jn][0] = *(const uint32_t*)(sBh + rb * RSTR + c0);
                Bhf[jn][1] = *(const uint32_t*)(sBh + rb * RSTR + c2);
                Blf[jn][0] = *(const uint32_t*)(sBl + rb * RSTR + c0);
                Blf[jn][1] = *(const uint32_t*)(sBl + rb * RSTR + c2);
            }
            #pragma unroll
            for (int im = 0; im < 4; im++) {
                int r0 = wm * 64 + im * 16 + gr;
                uint32_t Af[4], Afl[4];
                Af[0]  = *(const uint32_t*)(sAh + r0 * RSTR + c0);
                Af[1]  = *(const uint32_t*)(sAh + (r0 + 8) * RSTR + c0);
                Af[2]  = *(const uint32_t*)(sAh + r0 * RSTR + c2);
                Af[3]  = *(const uint32_t*)(sAh + (r0 + 8) * RSTR + c2);
                Afl[0] = *(const uint32_t*)(sAl + r0 * RSTR + c0);
                Afl[1] = *(const uint32_t*)(sAl + (r0 + 8) * RSTR + c0);
                Afl[2] = *(const uint32_t*)(sAl + r0 * RSTR + c2);
                Afl[3] = *(const uint32_t*)(sAl + (r0 + 8) * RSTR + c2);
                #pragma unroll
                for (int jn = 0; jn < 8; jn++) {
                    mma16816(acc[im][jn], Af,  Bhf[jn]);
                    mma16816(acc[im][jn], Af,  Blf[jn]);
                    mma16816(acc[im][jn], Afl, Bhf[jn]);
                }
            }
        }
        __syncthreads();
        if (t + 2 < T) load_stage(t & 1, (t + 2) * BK2);
    }

    // ---- epilogue ----
    if (OUTF) Cf += z * sC;
    if (OUTH) { Ch += z * sC; Cl += z * sC; }

    #pragma unroll
    for (int im = 0; im < 4; im++) {
        #pragma unroll
        for (int half = 0; half < 2; half++) {
            int r = row0 + wm * 64 + im * 16 + gr + half * 8;
            if (r >= M) continue;
            #pragma unroll
            for (int jn = 0; jn < 8; jn++) {
                int c = col0 + wn * 64 + jn * 8 + 2 * qp;
                float v0 = acc[im][jn][half * 2 + 0];
                float v1 = acc[im][jn][half * 2 + 1];
                if (MODE == 1) { v0 += bias[c]; v1 += bias[c + 1]; }
                else if (MODE == 2) {
                    const float* e = extra + ((r & (RPB - 1)) >> 2) * D_;
                    v0 += bias[c] + e[c]; v1 += bias[c + 1] + e[c + 1];
                }
                else if (MODE == 3) { v0 *= alpha; v1 *= alpha; }
                else if (MODE == 4) {
                    v0 += bias[c]; v1 += bias[c + 1];
                    v0 = 0.5f * v0 * (1.0f + erff(v0 * 0.7071067811865476f));
                    v1 = 0.5f * v1 * (1.0f + erff(v1 * 0.7071067811865476f));
                }
                else if (MODE == 5) {
                    const float* e = extra + (long)r * N;
                    v0 += bias[c] + e[c]; v1 += bias[c + 1] + e[c + 1];
                }
                else if (MODE == 6) { v0 += bias[r]; v1 += bias[r]; }

                if (OUTF)
                    *reinterpret_cast<float2*>(Cf + (long)r * N + c) = make_float2(v0, v1);
                if (OUTH) {
                    bf h0 = __float2bfloat16_rn(v0);
                    bf h1 = __float2bfloat16_rn(v1);
                    bf l0 = __float2bfloat16_rn(v0 - __bfloat162float(h0));
                    bf l1 = __float2bfloat16_rn(v1 - __bfloat162float(h1));
                    __nv_bfloat162 hp = __nv_bfloat162(h0, h1);
                    __nv_bfloat162 lp = __nv_bfloat162(l0, l1);
                    *reinterpret_cast<uint32_t*>(Ch + (long)r * N + c) = *reinterpret_cast<uint32_t*>(&hp);
                    *reinterpret_cast<uint32_t*>(Cl + (long)r * N + c) = *reinterpret_cast<uint32_t*>(&lp);
                }
            }
        }
    }
}

// ---------------- fp32 -> bf16 hi/lo split ----------------
__global__ void split_kernel(const float* __restrict__ x,
                             bf* __restrict__ h, bf* __restrict__ l, long n)
{
    for (long i = (long)blockIdx.x * blockDim.x + threadIdx.x; i < n;
         i += (long)gridDim.x * blockDim.x) {
        float v = x[i];
        bf hh = __float2bfloat16_rn(v);
        h[i] = hh;
        l[i] = __float2bfloat16_rn(v - __bfloat162float(hh));
    }
}

// ---------------- block reductions (256 threads) ----------------
__device__ __forceinline__ float blk_sum(float v) {
    __shared__ float sh[8];
    int tid = threadIdx.x;
    #pragma unroll
    for (int o = 16; o > 0; o >>= 1) v += __shfl_down_sync(0xffffffffu, v, o);
    if ((tid & 31) == 0) sh[tid >> 5] = v;
    __syncthreads();
    if (tid == 0) {
        float t = sh[0];
        #pragma unroll
        for (int w = 1; w < 8; w++) t += sh[w];
        sh[0] = t;
    }
    __syncthreads();
    float r = sh[0];
    __syncthreads();
    return r;
}

__device__ __forceinline__ float blk_max(float v) {
    __shared__ float sh[8];
    int tid = threadIdx.x;
    #pragma unroll
    for (int o = 16; o > 0; o >>= 1) v = fmaxf(v, __shfl_down_sync(0xffffffffu, v, o));
    if ((tid & 31) == 0) sh[tid >> 5] = v;
    __syncthreads();
    if (tid == 0) {
        float t = sh[0];
        #pragma unroll
        for (int w = 1; w < 8; w++) t = fmaxf(t, sh[w]);
        sh[0] = t;
    }
    __syncthreads();
    float r = sh[0];
    __syncthreads();
    return r;
}

// ---------------- slot init: fp32 + hi/lo ----------------
__global__ void init_slots_kernel(const float* __restrict__ noise,
                                  const float* __restrict__ mu,
                                  const float* __restrict__ sg,
                                  float* __restrict__ slots,
                                  bf* __restrict__ sh_, bf* __restrict__ sl_)
{
    const long total = (long)R_ * D_;
    for (long idx = (long)blockIdx.x * blockDim.x + threadIdx.x; idx < total;
         idx += (long)gridDim.x * blockDim.x) {
        int  d  = (int)(idx % D_);
        long r  = idx / D_;
        int  s  = (int)(r & 3);
        int  ii = (int)((r >> 2) & 63);
        int  bb = (int)(r >> 8);
        long ni = (((long)ii * B_ + bb) * S_ + s) * D_ + d;
        float v = mu[s * D_ + d] + noise[ni] * sg[s * D_ + d];
        slots[idx] = v;
        bf hh = __float2bfloat16_rn(v);
        sh_[idx] = hh;
        sl_[idx] = __float2bfloat16_rn(v - __bfloat162float(hh));
    }
}

// ---------------- softmax over N_=1024; emits attn hi/lo ----------------
__global__ __launch_bounds__(256)
void softmax_kernel(const float* __restrict__ logits,
                    bf* __restrict__ ah, bf* __restrict__ al)
{
    const float* p = logits + (long)blockIdx.x * N_;
    bf* ph = ah + (long)blockIdx.x * N_;
    bf* pl = al + (long)blockIdx.x * N_;
    int tid = threadIdx.x;
    float x[4];
    float m = -1e30f;
    #pragma unroll
    for (int j = 0; j < 4; j++) { x[j] = p[tid + j * 256]; m = fmaxf(m, x[j]); }
    m = blk_max(m);
    float s = 0.f;
    #pragma unroll
    for (int j = 0; j < 4; j++) { x[j] = expf(x[j] - m); s += x[j]; }
    s = blk_sum(s);
    float inv = 1.0f / s;
    #pragma unroll
    for (int j = 0; j < 4; j++) {
        float v = x[j] * inv;
        bf hh = __float2bfloat16_rn(v);
        ph[tid + j * 256] = hh;
        pl[tid + j * 256] = __float2bfloat16_rn(v - __bfloat162float(hh));
    }
}

// ---------------- fused: slots = LN1(slots+upd); hln(hi/lo) = LN2(slots) ----------------
__global__ __launch_bounds__(256)
void ln_fused_kernel(float* __restrict__ slots, const float* __restrict__ upd,
                     const float* __restrict__ g1, const float* __restrict__ b1,
                     const float* __restrict__ g2, const float* __restrict__ b2,
                     bf* __restrict__ hh, bf* __restrict__ hl)
{
    const long row = blockIdx.x;
    float*       sp = slots + row * D_;
    const float* up = upd   + row * D_;
    int tid = threadIdx.x;

    float x[3];
    float s = 0.f;
    #pragma unroll
    for (int j = 0; j < 3; j++) {
        int c = tid + j * 256;
        x[j] = sp[c] + up[c];
        s += x[j];
    }
    float mu = blk_sum(s) * (1.0f / D_);
    float vs = 0.f;
    #pragma unroll
    for (int j = 0; j < 3; j++) { x[j] -= mu; vs += x[j] * x[j]; }
    float rs = rsqrtf(blk_sum(vs) * (1.0f / D_) + 1e-5f);

    float y[3];
    float s2 = 0.f;
    #pragma unroll
    for (int j = 0; j < 3; j++) {
        int c = tid + j * 256;
        y[j] = x[j] * rs * g1[c] + b1[c];
        sp[c] = y[j];
        s2 += y[j];
    }
    float mu2 = blk_sum(s2) * (1.0f / D_);
    float vs2 = 0.f;
    #pragma unroll
    for (int j = 0; j < 3; j++) { float t = y[j] - mu2; vs2 += t * t; }
    float rs2 = rsqrtf(blk_sum(vs2) * (1.0f / D_) + 1e-5f);
    #pragma unroll
    for (int j = 0; j < 3; j++) {
        int c = tid + j * 256;
        float v = (y[j] - mu2) * rs2 * g2[c] + b2[c];
        bf h0 = __float2bfloat16_rn(v);
        hh[row * D_ + c] = h0;
        hl[row * D_ + c] = __float2bfloat16_rn(v - __bfloat162float(h0));
    }
}

// ---------------- scoring ----------------
__global__ __launch_bounds__(256)
void score_kernel(const float* __restrict__ slots, const float* __restrict__ iq,
                  float* __restrict__ out)
{
    int i = blockIdx.x;
    int b = blockIdx.y;
    int tid = threadIdx.x;

    float q[3];
    float qq = 0.f;
    #pragma unroll
    for (int j = 0; j < 3; j++) {
        q[j] = iq[i * D_ + tid + j * 256];
        qq += q[j] * q[j];
    }
    qq = blk_sum(qq);
    float qn = fmaxf(sqrtf(qq), 1e-12f);

    float score = 0.f;
    for (int s = 0; s < S_; s++) {
        const float* sp = slots + (((long)(b * I_ + i) * S_) + s) * D_;
        float ss = 0.f, sq = 0.f;
        #pragma unroll
        for (int j = 0; j < 3; j++) {
            float v = sp[tid + j * 256];
            ss += v * v;
            sq += v * q[j];
        }
        ss = blk_sum(ss);
        sq = blk_sum(sq);
        score += sq / (fmaxf(sqrtf(ss), 1e-12f) * qn);
    }
    if (tid == 0) out[(long)b * I_ + i] = score;
}

// ---------------- host orchestration ----------------
static inline float* sym(const void* s) {
    void* p = nullptr;
    cudaGetSymbolAddress(&p, s);
    return (float*)p;
}

extern "C" void kernel_launch(void* const* d_in, const int* in_sizes, int n_in,
                              void* d_out, int out_size)
{
    const float* tokens   = (const float*)d_in[0];
    const float* iq       = (const float*)d_in[1];
    const float* noise    = (const float*)d_in[2];
    const float* slot_mu  = (const float*)d_in[3];
    const float* slot_sg  = (const float*)d_in[4];
    const float* Wq_slot  = (const float*)d_in[5];
    const float* bq_slot  = (const float*)d_in[6];
    const float* Wq_int   = (const float*)d_in[7];
    const float* bq_int   = (const float*)d_in[8];
    const float* Wk       = (const float*)d_in[9];
    const float* bk       = (const float*)d_in[10];
    const float* Wv       = (const float*)d_in[11];
    const float* bv       = (const float*)d_in[12];
    const float* ln_s_g   = (const float*)d_in[13];
    const float* ln_s_b   = (const float*)d_in[14];
    const float* ln_m_g   = (const float*)d_in[15];
    const float* ln_m_b   = (const float*)d_in[16];
    const float* W1       = (const float*)d_in[17];
    const float* b1       = (const float*)d_in[18];
    const float* W2       = (const float*)d_in[19];
    const float* b2       = (const float*)d_in[20];
    float* out = (float*)d_out;

    bf* tokh = (bf*)sym(g_tokh); bf* tokl = (bf*)sym(g_tokl);
    bf* kh   = (bf*)sym(g_kh);   bf* kl   = (bf*)sym(g_kl);
    bf* vTh  = (bf*)sym(g_vTh);  bf* vTl  = (bf*)sym(g_vTl);
    bf* Wkh  = (bf*)sym(g_Wkh);  bf* Wkl  = (bf*)sym(g_Wkl);
    bf* Wvh  = (bf*)sym(g_Wvh);  bf* Wvl  = (bf*)sym(g_Wvl);
    bf* Wqsh = (bf*)sym(g_Wqsh); bf* Wqsl = (bf*)sym(g_Wqsl);
    bf* Wqih = (bf*)sym(g_Wqih); bf* Wqil = (bf*)sym(g_Wqil);
    bf* W1h  = (bf*)sym(g_W1h);  bf* W1l  = (bf*)sym(g_W1l);
    bf* W2h  = (bf*)sym(g_W2h);  bf* W2l  = (bf*)sym(g_W2l);
    bf* iqh  = (bf*)sym(g_iqh);  bf* iql  = (bf*)sym(g_iql);
    bf* sh_  = (bf*)sym(g_sh);   bf* sl_  = (bf*)sym(g_sl);
    bf* qsh  = (bf*)sym(g_qsh);  bf* qsl  = (bf*)sym(g_qsl);
    bf* ah   = (bf*)sym(g_ah);   bf* al   = (bf*)sym(g_al);
    bf* hlnh = (bf*)sym(g_hlnh); bf* hlnl = (bf*)sym(g_hlnl);
    bf* hmh  = (bf*)sym(g_hmh);  bf* hml  = (bf*)sym(g_hml);
    float* qint   = sym(g_qint);
    float* slots  = sym(g_slots);
    float* logits = sym(g_logits);
    float* upd    = sym(g_upd);

    cudaFuncSetAttribute(gemm2<0, true,  false>, cudaFuncAttributeMaxDynamicSharedMemorySize, GM_SMEM);
    cudaFuncSetAttribute(gemm2<1, false, true >, cudaFuncAttributeMaxDynamicSharedMemorySize, GM_SMEM);
    cudaFuncSetAttribute(gemm2<1, true,  false>, cudaFuncAttributeMaxDynamicSharedMemorySize, GM_SMEM);
    cudaFuncSetAttribute(gemm2<2, false, true >, cudaFuncAttributeMaxDynamicSharedMemorySize, GM_SMEM);
    cudaFuncSetAttribute(gemm2<3, true,  false>, cudaFuncAttributeMaxDynamicSharedMemorySize, GM_SMEM);
    cudaFuncSetAttribute(gemm2<4, false, true >, cudaFuncAttributeMaxDynamicSharedMemorySize, GM_SMEM);
    cudaFuncSetAttribute(gemm2<5, true,  true >, cudaFuncAttributeMaxDynamicSharedMemorySize, GM_SMEM);
    cudaFuncSetAttribute(gemm2<6, false, true >, cudaFuncAttributeMaxDynamicSharedMemorySize, GM_SMEM);

    const float scale = 0.036084391824351615f;  // 1/sqrt(768)
    const int BNtok = B_ * N_;                  // 32768

    // ---- one-time splits ----
    split_kernel<<<2048, 256>>>(tokens,  tokh, tokl, (long)BNtok * D_);
    split_kernel<<<512,  256>>>(Wk,      Wkh,  Wkl,  (long)D_ * D_);
    split_kernel<<<512,  256>>>(Wv,      Wvh,  Wvl,  (long)D_ * D_);
    split_kernel<<<512,  256>>>(Wq_slot, Wqsh, Wqsl, (long)D_ * D_);
    split_kernel<<<512,  256>>>(Wq_int,  Wqih, Wqil, (long)D_ * D_);
    split_kernel<<<512,  256>>>(W1,      W1h,  W1l,  (long)D2_ * D_);
    split_kernel<<<512,  256>>>(W2,      W2h,  W2l,  (long)D_ * D2_);
    split_kernel<<<64,   256>>>(iq,      iqh,  iql,  (long)I_ * D_);

    // k = tokens x Wk^T + bk -> hi/lo   [32768, 768]
    gemm2<1, false, true><<<dim3(D_ / BN2, BNtok / BM2, 1), 256, GM_SMEM>>>(
        tokh, tokl, Wkh, Wkl, nullptr, kh, kl,
        BNtok, D_, D_, 0, 0, 0, bk, nullptr, 1.f);

    // vT[b] = Wv x tokens[b]^T + bv[row] -> hi/lo   [768, 1024] per b
    gemm2<6, false, true><<<dim3(N_ / BN2, D_ / BM2, B_), 256, GM_SMEM>>>(
        Wvh, Wvl, tokh, tokl, nullptr, vTh, vTl,
        D_, N_, D_, 0, (long)N_ * D_, (long)D_ * N_, bv, nullptr, 1.f);

    // q_intent = iq x Wq_int^T + bq_int -> fp32   [64, 768] (M guarded)
    gemm2<1, true, false><<<dim3(D_ / BN2, 1, 1), 256, GM_SMEM>>>(
        iqh, iql, Wqih, Wqil, qint, nullptr, nullptr,
        I_, D_, D_, 0, 0, 0, bq_int, nullptr, 1.f);

    init_slots_kernel<<<2048, 256>>>(noise, slot_mu, slot_sg, slots, sh_, sl_);

    for (int it = 0; it < 3; it++) {
        // q_slot = slots x Wq_slot^T + bq_slot + qint[i] -> hi/lo
        gemm2<2, false, true><<<dim3(D_ / BN2, R_ / BM2, 1), 256, GM_SMEM>>>(
            sh_, sl_, Wqsh, Wqsl, nullptr, qsh, qsl,
            R_, D_, D_, 0, 0, 0, bq_slot, qint, 1.f);

        // logits[b] = q_slot[b] x k[b]^T * scale -> fp32
        gemm2<3, true, false><<<dim3(N_ / BN2, RPB / BM2, B_), 256, GM_SMEM>>>(
            qsh, qsl, kh, kl, logits, nullptr, nullptr,
            RPB, N_, D_, (long)RPB * D_, (long)N_ * D_, (long)RPB * N_,
            nullptr, nullptr, scale);

        softmax_kernel<<<R_, 256>>>(logits, ah, al);

        // upd[b] = attn[b] x vT[b]^T -> fp32   (K = 1024)
        gemm2<0, true, false><<<dim3(D_ / BN2, RPB / BM2, B_), 256, GM_SMEM>>>(
            ah, al, vTh, vTl, upd, nullptr, nullptr,
            RPB, D_, N_, (long)RPB * N_, (long)D_ * N_, (long)RPB * D_,
            nullptr, nullptr, 1.f);

        // slots = LN1(slots + upd); hln(hi/lo) = LN2(slots)
        ln_fused_kernel<<<R_, 256>>>(slots, upd, ln_s_g, ln_s_b, ln_m_g, ln_m_b,
                                     hlnh, hlnl);

        // hmid = gelu(hln x W1^T + b1) -> hi/lo
        gemm2<4, false, true><<<dim3(D2_ / BN2, R_ / BM2, 1), 256, GM_SMEM>>>(
            hlnh, hlnl, W1h, W1l, nullptr, hmh, hml,
            R_, D2_, D_, 0, 0, 0, b1, nullptr, 1.f);

        // slots = slots + hmid x W2^T + b2 -> fp32 + hi/lo   (K = 1536)
        gemm2<5, true, true><<<dim3(D_ / BN2, R_ / BM2, 1), 256, GM_SMEM>>>(
            hmh, hml, W2h, W2l, slots, sh_, sl_,
            R_, D_, D2_, 0, 0, 0, b2, slots, 1.f);
    }

    score_kernel<<<dim3(I_, B_), 256>>>(slots, iq, out);
}